// round 4
// baseline (speedup 1.0000x reference)
#include <cuda_runtime.h>
#include <cstdint>

#define E_CNT   100000
#define N_NODES 50000
#define H_CNT   4
#define D_CNT   128
#define NCAND   (3 * E_CNT)          // 300000 candidate (entry, type) pairs
#define ALPHA   0.2f

// ---------------------------------------------------------------------------
// Scratch (device globals — no allocation allowed in kernel_launch).
// ---------------------------------------------------------------------------
__device__ int g_count [N_NODES];   // candidates per node
__device__ int g_off   [N_NODES];   // exclusive-scan start offsets
__device__ int g_cursor[N_NODES];   // fill cursors (copy of g_off, consumed)
__device__ int g_list  [NCAND];     // candidate ids t = i*E + e, grouped by node

// ---------------------------------------------------------------------------
// Kernel 1: zero the per-node counters.
// ---------------------------------------------------------------------------
__global__ void zero_kernel() {
    int g = blockIdx.x * blockDim.x + threadIdx.x;
    if (g < N_NODES) g_count[g] = 0;
}

// ---------------------------------------------------------------------------
// Kernel 2: histogram — one thread per candidate t.
// node(t) = batch[e*3 + i] with t = i*E + e.
// ---------------------------------------------------------------------------
__global__ void hist_kernel(const int* __restrict__ batch) {
    int t = blockIdx.x * blockDim.x + threadIdx.x;
    if (t >= NCAND) return;
    int i = t / E_CNT;
    int e = t - i * E_CNT;
    int node = batch[e * 3 + i];
    atomicAdd(&g_count[node], 1);
}

// ---------------------------------------------------------------------------
// Kernel 3: single-block blocked exclusive scan of g_count -> g_off, g_cursor.
// 1024 threads, each owns a contiguous chunk of ~49 nodes.
// ---------------------------------------------------------------------------
__global__ void __launch_bounds__(1024) scan_kernel() {
    __shared__ int partial[1024];
    const int T = 1024;
    const int chunk = (N_NODES + T - 1) / T;   // 49
    int tid = threadIdx.x;
    int begin = tid * chunk;
    int end   = begin + chunk; if (end > N_NODES) end = N_NODES;

    int s = 0;
    for (int j = begin; j < end; j++) s += g_count[j];
    partial[tid] = s;
    __syncthreads();

    // Hillis-Steele inclusive scan over the 1024 partials
    for (int off = 1; off < T; off <<= 1) {
        int v   = partial[tid];
        int add = (tid >= off) ? partial[tid - off] : 0;
        __syncthreads();
        partial[tid] = v + add;
        __syncthreads();
    }

    int run = (tid == 0) ? 0 : partial[tid - 1];
    for (int j = begin; j < end; j++) {
        g_off[j]    = run;
        g_cursor[j] = run;
        run += g_count[j];
    }
}

// ---------------------------------------------------------------------------
// Kernel 4: fill candidate lists (order within a node is irrelevant:
// max is order-invariant over identical per-candidate values).
// ---------------------------------------------------------------------------
__global__ void fill_kernel(const int* __restrict__ batch) {
    int t = blockIdx.x * blockDim.x + threadIdx.x;
    if (t >= NCAND) return;
    int i = t / E_CNT;
    int e = t - i * E_CNT;
    int node = batch[e * 3 + i];
    int pos = atomicAdd(&g_cursor[node], 1);
    g_list[pos] = t;
}

// ---------------------------------------------------------------------------
// Kernel 5: gather. One block per node, 128 threads.
//   warp = head h (tid>>5), lanes cover d in float4 chunks (d0 = (tid&31)*4).
// For each candidate t of this node: v[d] = w[t,h,0]*f(n0)[d] + w[t,h,1]*f(n1)[d]
// running max in registers; epilogue adds residual + leaky-relu and stores.
// Weight row index IS t (blocks of att_weights are laid out i-major).
// ---------------------------------------------------------------------------
__global__ void __launch_bounds__(128) gather_kernel(
    const int*   __restrict__ batch,   // [E, 3]
    const float* __restrict__ feats,   // [N, 128]
    const float* __restrict__ w,       // [3E, 4, 2]
    float*       __restrict__ out)     // [N, 4, 128]
{
    const int node = blockIdx.x;
    const int tid  = threadIdx.x;
    const int h    = tid >> 5;
    const int d0   = (tid & 31) << 2;

    const int start = g_off[node];
    const int cnt   = g_count[node];

    const float NEG_INF = __int_as_float(0xff800000);
    float4 m = make_float4(NEG_INF, NEG_INF, NEG_INF, NEG_INF);

    for (int k = 0; k < cnt; k++) {
        const int t = g_list[start + k];
        const int i = t / E_CNT;
        const int e = t - i * E_CNT;

        // columns != i, in ascending order (matches reference gather order;
        // order doesn't matter for max anyway, but weights pair w/ columns)
        const int c0 = (i == 0) ? 1 : 0;
        const int c1 = (i == 2) ? 1 : 2;
        const int n0 = batch[e * 3 + c0];
        const int n1 = batch[e * 3 + c1];

        const float2 wv = *(const float2*)(w + ((long)t * H_CNT + h) * 2);

        const float4 f0 = *(const float4*)(feats + (long)n0 * D_CNT + d0);
        const float4 f1 = *(const float4*)(feats + (long)n1 * D_CNT + d0);

        float vx = fmaf(wv.x, f0.x, wv.y * f1.x);
        float vy = fmaf(wv.x, f0.y, wv.y * f1.y);
        float vz = fmaf(wv.x, f0.z, wv.y * f1.z);
        float vw = fmaf(wv.x, f0.w, wv.y * f1.w);

        m.x = fmaxf(m.x, vx);
        m.y = fmaxf(m.y, vy);
        m.z = fmaxf(m.z, vz);
        m.w = fmaxf(m.w, vw);
    }

    // residual + leaky-relu (every node guaranteed non-empty by construction)
    const float4 f = *(const float4*)(feats + (long)node * D_CNT + d0);
    float4 v;
    v.x = m.x + f.x;  v.y = m.y + f.y;  v.z = m.z + f.z;  v.w = m.w + f.w;
    v.x = (v.x >= 0.f) ? v.x : ALPHA * v.x;
    v.y = (v.y >= 0.f) ? v.y : ALPHA * v.y;
    v.z = (v.z >= 0.f) ? v.z : ALPHA * v.z;
    v.w = (v.w >= 0.f) ? v.w : ALPHA * v.w;

    *(float4*)(out + (long)node * (H_CNT * D_CNT) + h * D_CNT + d0) = v;
}

extern "C" void kernel_launch(void* const* d_in, const int* in_sizes, int n_in,
                              void* d_out, int out_size) {
    const int*   batch = (const int*)  d_in[0];   // [E, 3] int32
    const float* feats = (const float*)d_in[1];   // [N, 128] f32
    const float* w     = (const float*)d_in[2];   // [3E, 4, 2] f32
    float*       out   = (float*)d_out;           // [N, 512] f32

    zero_kernel<<<(N_NODES + 255) / 256, 256>>>();
    hist_kernel<<<(NCAND + 255) / 256, 256>>>(batch);
    scan_kernel<<<1, 1024>>>();
    fill_kernel<<<(NCAND + 255) / 256, 256>>>(batch);
    gather_kernel<<<N_NODES, 128>>>(batch, feats, w, out);
}

// round 6
// speedup vs baseline: 1.0464x; 1.0464x over previous
#include <cuda_runtime.h>
#include <cstdint>

#define E_CNT   100000
#define N_NODES 50000
#define H_CNT   4
#define D_CNT   128
#define NCAND   (3 * E_CNT)          // 300000 candidate (entry, type) pairs
#define ALPHA   0.2f

// ---------------------------------------------------------------------------
// Scratch (device globals — allocation in kernel_launch is forbidden).
// ---------------------------------------------------------------------------
__device__ int  g_count [N_NODES];   // candidates per node
__device__ int  g_off   [N_NODES];   // exclusive-scan start offsets
__device__ int  g_cursor[N_NODES];   // fill cursors
__device__ int4 g_rec   [NCAND];     // {t, n0, n1, 0} grouped by node

// ---------------------------------------------------------------------------
// Kernel 1: zero per-node counters.
// ---------------------------------------------------------------------------
__global__ void zero_kernel() {
    int g = blockIdx.x * blockDim.x + threadIdx.x;
    if (g < N_NODES) g_count[g] = 0;
}

// ---------------------------------------------------------------------------
// Kernel 2: histogram — one thread per candidate t (t = i*E + e).
// ---------------------------------------------------------------------------
__global__ void hist_kernel(const int* __restrict__ batch) {
    int t = blockIdx.x * blockDim.x + threadIdx.x;
    if (t >= NCAND) return;
    int i = t / E_CNT;
    int e = t - i * E_CNT;
    atomicAdd(&g_count[batch[e * 3 + i]], 1);
}

// ---------------------------------------------------------------------------
// Kernel 3: single-block blocked exclusive scan (50K elements, 1024 threads).
// ---------------------------------------------------------------------------
__global__ void __launch_bounds__(1024) scan_kernel() {
    __shared__ int partial[1024];
    const int T = 1024;
    const int chunk = (N_NODES + T - 1) / T;   // 49
    int tid = threadIdx.x;
    int begin = tid * chunk;
    int end   = begin + chunk; if (end > N_NODES) end = N_NODES;

    int s = 0;
    #pragma unroll 7
    for (int j = begin; j < end; j++) s += g_count[j];
    partial[tid] = s;
    __syncthreads();

    for (int off = 1; off < T; off <<= 1) {
        int v   = partial[tid];
        int add = (tid >= off) ? partial[tid - off] : 0;
        __syncthreads();
        partial[tid] = v + add;
        __syncthreads();
    }

    int run = (tid == 0) ? 0 : partial[tid - 1];
    for (int j = begin; j < end; j++) {
        g_off[j]    = run;
        g_cursor[j] = run;
        run += g_count[j];
    }
}

// ---------------------------------------------------------------------------
// Kernel 4: fill candidate records {t, n0, n1}. Order within a node is
// irrelevant (max is order-invariant over identical values).
// ---------------------------------------------------------------------------
__global__ void fill_kernel(const int* __restrict__ batch) {
    int t = blockIdx.x * blockDim.x + threadIdx.x;
    if (t >= NCAND) return;
    int i = t / E_CNT;
    int e = t - i * E_CNT;
    const int c0 = (i == 0) ? 1 : 0;
    const int c1 = (i == 2) ? 1 : 2;
    int node = batch[e * 3 + i];
    int n0   = batch[e * 3 + c0];
    int n1   = batch[e * 3 + c1];
    int pos = atomicAdd(&g_cursor[node], 1);
    g_rec[pos] = make_int4(t, n0, n1, 0);
}

// ---------------------------------------------------------------------------
// Kernel 5: gather. One block per node, 128 threads (4 warps).
// Each WARP processes a disjoint subset of this node's candidates and
// computes ALL 4 heads from one pair of feature-row loads (4x traffic cut
// vs warp-per-head). Lanes cover D in float4 chunks. Cross-warp head-max
// reduction through smem, fused residual + leaky-relu epilogue.
// ---------------------------------------------------------------------------
__global__ void __launch_bounds__(128) gather_kernel(
    const float* __restrict__ feats,   // [N, 128]
    const float* __restrict__ w,       // [3E, 4, 2]
    float*       __restrict__ out)     // [N, 4, 128]
{
    __shared__ float sm[4][4][128];    // [warp][head][d]

    const int node = blockIdx.x;
    const int tid  = threadIdx.x;
    const int wid  = tid >> 5;
    const int lane = tid & 31;
    const int d0   = lane << 2;

    const int start = g_off[node];
    const int cnt   = g_count[node];

    const float NI = __int_as_float(0xff800000);
    float4 m0 = make_float4(NI, NI, NI, NI);
    float4 m1 = m0, m2 = m0, m3 = m0;

    for (int k = wid; k < cnt; k += 4) {
        const int4 r = g_rec[start + k];
        // 8 weights for candidate t=r.x: heads 0..3 x cols {c0,c1}
        const float4 wa = *(const float4*)(w + (long)r.x * 8);
        const float4 wb = *(const float4*)(w + (long)r.x * 8 + 4);
        const float4 f0 = *(const float4*)(feats + (long)r.y * D_CNT + d0);
        const float4 f1 = *(const float4*)(feats + (long)r.z * D_CNT + d0);

        m0.x = fmaxf(m0.x, fmaf(wa.x, f0.x, wa.y * f1.x));
        m0.y = fmaxf(m0.y, fmaf(wa.x, f0.y, wa.y * f1.y));
        m0.z = fmaxf(m0.z, fmaf(wa.x, f0.z, wa.y * f1.z));
        m0.w = fmaxf(m0.w, fmaf(wa.x, f0.w, wa.y * f1.w));

        m1.x = fmaxf(m1.x, fmaf(wa.z, f0.x, wa.w * f1.x));
        m1.y = fmaxf(m1.y, fmaf(wa.z, f0.y, wa.w * f1.y));
        m1.z = fmaxf(m1.z, fmaf(wa.z, f0.z, wa.w * f1.z));
        m1.w = fmaxf(m1.w, fmaf(wa.z, f0.w, wa.w * f1.w));

        m2.x = fmaxf(m2.x, fmaf(wb.x, f0.x, wb.y * f1.x));
        m2.y = fmaxf(m2.y, fmaf(wb.x, f0.y, wb.y * f1.y));
        m2.z = fmaxf(m2.z, fmaf(wb.x, f0.z, wb.y * f1.z));
        m2.w = fmaxf(m2.w, fmaf(wb.x, f0.w, wb.y * f1.w));

        m3.x = fmaxf(m3.x, fmaf(wb.z, f0.x, wb.w * f1.x));
        m3.y = fmaxf(m3.y, fmaf(wb.z, f0.y, wb.w * f1.y));
        m3.z = fmaxf(m3.z, fmaf(wb.z, f0.z, wb.w * f1.z));
        m3.w = fmaxf(m3.w, fmaf(wb.z, f0.w, wb.w * f1.w));
    }

    *(float4*)&sm[wid][0][d0] = m0;
    *(float4*)&sm[wid][1][d0] = m1;
    *(float4*)&sm[wid][2][d0] = m2;
    *(float4*)&sm[wid][3][d0] = m3;
    __syncthreads();

    // warp `wid` reduces head h = wid over the 4 warp-partials
    const float4 a = *(const float4*)&sm[0][wid][d0];
    const float4 b = *(const float4*)&sm[1][wid][d0];
    const float4 c = *(const float4*)&sm[2][wid][d0];
    const float4 d = *(const float4*)&sm[3][wid][d0];

    float4 m;
    m.x = fmaxf(fmaxf(a.x, b.x), fmaxf(c.x, d.x));
    m.y = fmaxf(fmaxf(a.y, b.y), fmaxf(c.y, d.y));
    m.z = fmaxf(fmaxf(a.z, b.z), fmaxf(c.z, d.z));
    m.w = fmaxf(fmaxf(a.w, b.w), fmaxf(c.w, d.w));

    const float4 f = *(const float4*)(feats + (long)node * D_CNT + d0);
    float4 v;
    v.x = m.x + f.x;  v.y = m.y + f.y;  v.z = m.z + f.z;  v.w = m.w + f.w;
    v.x = (v.x >= 0.f) ? v.x : ALPHA * v.x;
    v.y = (v.y >= 0.f) ? v.y : ALPHA * v.y;
    v.z = (v.z >= 0.f) ? v.z : ALPHA * v.z;
    v.w = (v.w >= 0.f) ? v.w : ALPHA * v.w;

    *(float4*)(out + (long)node * (H_CNT * D_CNT) + wid * D_CNT + d0) = v;
}

extern "C" void kernel_launch(void* const* d_in, const int* in_sizes, int n_in,
                              void* d_out, int out_size) {
    const int*   batch = (const int*)  d_in[0];   // [E, 3] int32
    const float* feats = (const float*)d_in[1];   // [N, 128] f32
    const float* w     = (const float*)d_in[2];   // [3E, 4, 2] f32
    float*       out   = (float*)d_out;           // [N, 512] f32

    zero_kernel<<<(N_NODES + 255) / 256, 256>>>();
    hist_kernel<<<(NCAND + 255) / 256, 256>>>(batch);
    scan_kernel<<<1, 1024>>>();
    fill_kernel<<<(NCAND + 255) / 256, 256>>>(batch);
    gather_kernel<<<N_NODES, 128>>>(feats, w, out);
}

// round 7
// speedup vs baseline: 1.9860x; 1.8979x over previous
#include <cuda_runtime.h>
#include <cstdint>

#define E_CNT   100000
#define N_NODES 50000
#define H_CNT   4
#define D_CNT   128
#define NCAND   (3 * E_CNT)          // 300000 candidate (entry, type) pairs
#define ALPHA   0.2f
#define SCAN_B  1024                 // scan tile size
#define NTILES  ((N_NODES + SCAN_B - 1) / SCAN_B)   // 49

// ---------------------------------------------------------------------------
// Scratch (device globals; zero-initialized at module load. Every run leaves
// g_count back at zero — scanA consumes-and-clears it — so graph replays see
// identical state).
// ---------------------------------------------------------------------------
__device__ int  g_count [N_NODES];       // candidates per node (zeroed by scanA)
__device__ int  g_off   [N_NODES + 1];   // global start offsets
__device__ int  g_cursor[N_NODES];       // fill cursors
__device__ int  g_bsum  [NTILES];        // per-tile totals
__device__ int4 g_rec   [NCAND];         // {t, n0, n1, 0} grouped by node

// ---------------------------------------------------------------------------
// Kernel 1: histogram — one thread per candidate t (t = i*E + e).
// Relies on g_count == 0 on entry (invariant maintained by scanA).
// ---------------------------------------------------------------------------
__global__ void hist_kernel(const int* __restrict__ batch) {
    int t = blockIdx.x * blockDim.x + threadIdx.x;
    if (t >= NCAND) return;
    int i = t / E_CNT;
    int e = t - i * E_CNT;
    atomicAdd(&g_count[batch[e * 3 + i]], 1);
}

// ---------------------------------------------------------------------------
// Kernel 2 (scanA): 49 blocks x 1024. Coalesced tile load of counts,
// zero the counts (restores invariant), block-local exclusive scan via
// warp shuffles, write local offsets to g_off and tile total to g_bsum.
// ---------------------------------------------------------------------------
__global__ void __launch_bounds__(SCAN_B) scanA_kernel() {
    __shared__ int ws[32];
    const int tid = threadIdx.x;
    const int j   = blockIdx.x * SCAN_B + tid;
    const int lane = tid & 31, wid = tid >> 5;

    int c = 0;
    if (j < N_NODES) { c = g_count[j]; g_count[j] = 0; }

    // warp inclusive scan
    int v = c;
    #pragma unroll
    for (int o = 1; o < 32; o <<= 1) {
        int t = __shfl_up_sync(0xffffffffu, v, o);
        if (lane >= o) v += t;
    }
    if (lane == 31) ws[wid] = v;
    __syncthreads();
    if (wid == 0) {
        int s = ws[lane];
        #pragma unroll
        for (int o = 1; o < 32; o <<= 1) {
            int t = __shfl_up_sync(0xffffffffu, s, o);
            if (lane >= o) s += t;
        }
        ws[lane] = s;
    }
    __syncthreads();

    int excl = v - c + (wid ? ws[wid - 1] : 0);
    if (j < N_NODES) g_off[j] = excl;            // local (pre-fixup) offset
    if (tid == SCAN_B - 1) g_bsum[blockIdx.x] = excl + c;
}

// ---------------------------------------------------------------------------
// Kernel 3 (scanB): 49 blocks. Each block reduces g_bsum[0..blk) (<=48 values,
// one warp), then adds that prefix to its tile of g_off and writes cursors.
// ---------------------------------------------------------------------------
__global__ void __launch_bounds__(SCAN_B) scanB_kernel() {
    __shared__ int s_prefix;
    const int tid = threadIdx.x;
    const int blk = blockIdx.x;

    if (tid < 32) {
        int s = 0;
        if (tid      < blk) s += g_bsum[tid];
        if (tid + 32 < blk) s += g_bsum[tid + 32];
        #pragma unroll
        for (int o = 16; o > 0; o >>= 1)
            s += __shfl_down_sync(0xffffffffu, s, o);
        if (tid == 0) s_prefix = s;
    }
    __syncthreads();
    const int prefix = s_prefix;

    int j = blk * SCAN_B + tid;
    if (j < N_NODES) {
        int off = g_off[j] + prefix;
        g_off[j]    = off;
        g_cursor[j] = off;
    }
    if (blk == 0 && tid == 0) g_off[N_NODES] = NCAND;
}

// ---------------------------------------------------------------------------
// Kernel 4: fill candidate records {t, n0, n1}. Order within a node is
// irrelevant (max over identical values is order-invariant -> deterministic).
// ---------------------------------------------------------------------------
__global__ void fill_kernel(const int* __restrict__ batch) {
    int t = blockIdx.x * blockDim.x + threadIdx.x;
    if (t >= NCAND) return;
    int i = t / E_CNT;
    int e = t - i * E_CNT;
    // whole batch row (12B, single 128B line)
    int b0 = batch[e * 3 + 0];
    int b1 = batch[e * 3 + 1];
    int b2 = batch[e * 3 + 2];
    int node = (i == 0) ? b0 : (i == 1) ? b1 : b2;
    int n0   = (i == 0) ? b1 : b0;
    int n1   = (i == 2) ? b1 : b2;
    int pos = atomicAdd(&g_cursor[node], 1);
    g_rec[pos] = make_int4(t, n0, n1, 0);
}

// ---------------------------------------------------------------------------
// Kernel 5: gather. One block per node, 128 threads (4 warps).
// Each warp takes a disjoint candidate subset and computes ALL 4 heads from
// one pair of feature-row loads. Cross-warp head-max via smem, fused
// residual + leaky-relu epilogue.
// ---------------------------------------------------------------------------
__global__ void __launch_bounds__(128) gather_kernel(
    const float* __restrict__ feats,   // [N, 128]
    const float* __restrict__ w,       // [3E, 4, 2]
    float*       __restrict__ out)     // [N, 4, 128]
{
    __shared__ float sm[4][4][128];    // [warp][head][d]

    const int node = blockIdx.x;
    const int tid  = threadIdx.x;
    const int wid  = tid >> 5;
    const int lane = tid & 31;
    const int d0   = lane << 2;

    const int start = g_off[node];
    const int end   = g_off[node + 1];

    const float NI = __int_as_float(0xff800000);
    float4 m0 = make_float4(NI, NI, NI, NI);
    float4 m1 = m0, m2 = m0, m3 = m0;

    for (int k = start + wid; k < end; k += 4) {
        const int4 r = g_rec[k];
        const float4 wa = *(const float4*)(w + (long)r.x * 8);      // heads 0,1
        const float4 wb = *(const float4*)(w + (long)r.x * 8 + 4);  // heads 2,3
        const float4 f0 = *(const float4*)(feats + (long)r.y * D_CNT + d0);
        const float4 f1 = *(const float4*)(feats + (long)r.z * D_CNT + d0);

        m0.x = fmaxf(m0.x, fmaf(wa.x, f0.x, wa.y * f1.x));
        m0.y = fmaxf(m0.y, fmaf(wa.x, f0.y, wa.y * f1.y));
        m0.z = fmaxf(m0.z, fmaf(wa.x, f0.z, wa.y * f1.z));
        m0.w = fmaxf(m0.w, fmaf(wa.x, f0.w, wa.y * f1.w));

        m1.x = fmaxf(m1.x, fmaf(wa.z, f0.x, wa.w * f1.x));
        m1.y = fmaxf(m1.y, fmaf(wa.z, f0.y, wa.w * f1.y));
        m1.z = fmaxf(m1.z, fmaf(wa.z, f0.z, wa.w * f1.z));
        m1.w = fmaxf(m1.w, fmaf(wa.z, f0.w, wa.w * f1.w));

        m2.x = fmaxf(m2.x, fmaf(wb.x, f0.x, wb.y * f1.x));
        m2.y = fmaxf(m2.y, fmaf(wb.x, f0.y, wb.y * f1.y));
        m2.z = fmaxf(m2.z, fmaf(wb.x, f0.z, wb.y * f1.z));
        m2.w = fmaxf(m2.w, fmaf(wb.x, f0.w, wb.y * f1.w));

        m3.x = fmaxf(m3.x, fmaf(wb.z, f0.x, wb.w * f1.x));
        m3.y = fmaxf(m3.y, fmaf(wb.z, f0.y, wb.w * f1.y));
        m3.z = fmaxf(m3.z, fmaf(wb.z, f0.z, wb.w * f1.z));
        m3.w = fmaxf(m3.w, fmaf(wb.z, f0.w, wb.w * f1.w));
    }

    *(float4*)&sm[wid][0][d0] = m0;
    *(float4*)&sm[wid][1][d0] = m1;
    *(float4*)&sm[wid][2][d0] = m2;
    *(float4*)&sm[wid][3][d0] = m3;
    __syncthreads();

    // warp `wid` reduces head h = wid over the 4 warp-partials
    const float4 a = *(const float4*)&sm[0][wid][d0];
    const float4 b = *(const float4*)&sm[1][wid][d0];
    const float4 c = *(const float4*)&sm[2][wid][d0];
    const float4 d = *(const float4*)&sm[3][wid][d0];

    float4 m;
    m.x = fmaxf(fmaxf(a.x, b.x), fmaxf(c.x, d.x));
    m.y = fmaxf(fmaxf(a.y, b.y), fmaxf(c.y, d.y));
    m.z = fmaxf(fmaxf(a.z, b.z), fmaxf(c.z, d.z));
    m.w = fmaxf(fmaxf(a.w, b.w), fmaxf(c.w, d.w));

    const float4 f = *(const float4*)(feats + (long)node * D_CNT + d0);
    float4 v;
    v.x = m.x + f.x;  v.y = m.y + f.y;  v.z = m.z + f.z;  v.w = m.w + f.w;
    v.x = (v.x >= 0.f) ? v.x : ALPHA * v.x;
    v.y = (v.y >= 0.f) ? v.y : ALPHA * v.y;
    v.z = (v.z >= 0.f) ? v.z : ALPHA * v.z;
    v.w = (v.w >= 0.f) ? v.w : ALPHA * v.w;

    *(float4*)(out + (long)node * (H_CNT * D_CNT) + wid * D_CNT + d0) = v;
}

extern "C" void kernel_launch(void* const* d_in, const int* in_sizes, int n_in,
                              void* d_out, int out_size) {
    const int*   batch = (const int*)  d_in[0];   // [E, 3] int32
    const float* feats = (const float*)d_in[1];   // [N, 128] f32
    const float* w     = (const float*)d_in[2];   // [3E, 4, 2] f32
    float*       out   = (float*)d_out;           // [N, 512] f32

    hist_kernel <<<(NCAND + 255) / 256, 256>>>(batch);
    scanA_kernel<<<NTILES, SCAN_B>>>();
    scanB_kernel<<<NTILES, SCAN_B>>>();
    fill_kernel <<<(NCAND + 255) / 256, 256>>>(batch);
    gather_kernel<<<N_NODES, 128>>>(feats, w, out);
}

// round 8
// speedup vs baseline: 2.4526x; 1.2349x over previous
#include <cuda_runtime.h>
#include <cstdint>

#define E_CNT   100000
#define N_NODES 50000
#define H_CNT   4
#define D_CNT   128
#define NCAND   (3 * E_CNT)          // 300000 candidate (entry, type) pairs
#define ALPHA   0.2f
#define SCAN_B  1024
#define NTILES  ((N_NODES + SCAN_B - 1) / SCAN_B)   // 49
#define NODES_PER_BLK 8              // warp-per-node gather

// ---------------------------------------------------------------------------
// Scratch (device globals; zero-initialized at module load. Every run leaves
// g_count back at zero — scanA consumes-and-clears it — so graph replays see
// identical state).
// ---------------------------------------------------------------------------
__device__ int  g_count [N_NODES];       // candidates per node (zeroed by scanA)
__device__ int  g_off   [N_NODES + 1];   // global start offsets
__device__ int  g_cursor[N_NODES];       // fill cursors
__device__ int  g_bsum  [NTILES];        // per-tile totals
__device__ int4 g_rec   [NCAND];         // {t, n0, n1, 0} grouped by node

// ---------------------------------------------------------------------------
// Kernel 1: histogram — one thread per ENTRY e; 3 counter bumps from one
// 12-byte batch-row read. Relies on g_count == 0 on entry.
// ---------------------------------------------------------------------------
__global__ void hist_kernel(const int* __restrict__ batch) {
    int e = blockIdx.x * blockDim.x + threadIdx.x;
    if (e >= E_CNT) return;
    int b0 = batch[e * 3 + 0];
    int b1 = batch[e * 3 + 1];
    int b2 = batch[e * 3 + 2];
    atomicAdd(&g_count[b0], 1);
    atomicAdd(&g_count[b1], 1);
    atomicAdd(&g_count[b2], 1);
}

// ---------------------------------------------------------------------------
// Kernel 2 (scanA): 49 blocks x 1024. Coalesced tile load of counts, zero
// the counts, block-local exclusive scan via warp shuffles, write local
// offsets to g_off and tile total to g_bsum.
// ---------------------------------------------------------------------------
__global__ void __launch_bounds__(SCAN_B) scanA_kernel() {
    __shared__ int ws[32];
    const int tid = threadIdx.x;
    const int j   = blockIdx.x * SCAN_B + tid;
    const int lane = tid & 31, wid = tid >> 5;

    int c = 0;
    if (j < N_NODES) { c = g_count[j]; g_count[j] = 0; }

    int v = c;
    #pragma unroll
    for (int o = 1; o < 32; o <<= 1) {
        int t = __shfl_up_sync(0xffffffffu, v, o);
        if (lane >= o) v += t;
    }
    if (lane == 31) ws[wid] = v;
    __syncthreads();
    if (wid == 0) {
        int s = ws[lane];
        #pragma unroll
        for (int o = 1; o < 32; o <<= 1) {
            int t = __shfl_up_sync(0xffffffffu, s, o);
            if (lane >= o) s += t;
        }
        ws[lane] = s;
    }
    __syncthreads();

    int excl = v - c + (wid ? ws[wid - 1] : 0);
    if (j < N_NODES) g_off[j] = excl;
    if (tid == SCAN_B - 1) g_bsum[blockIdx.x] = excl + c;
}

// ---------------------------------------------------------------------------
// Kernel 3 (scanB): add tile prefixes (<=48 values, one warp per block),
// materialize cursors and the end sentinel.
// ---------------------------------------------------------------------------
__global__ void __launch_bounds__(SCAN_B) scanB_kernel() {
    __shared__ int s_prefix;
    const int tid = threadIdx.x;
    const int blk = blockIdx.x;

    if (tid < 32) {
        int s = 0;
        if (tid      < blk) s += g_bsum[tid];
        if (tid + 32 < blk) s += g_bsum[tid + 32];
        #pragma unroll
        for (int o = 16; o > 0; o >>= 1)
            s += __shfl_down_sync(0xffffffffu, s, o);
        if (tid == 0) s_prefix = s;
    }
    __syncthreads();
    const int prefix = s_prefix;

    int j = blk * SCAN_B + tid;
    if (j < N_NODES) {
        int off = g_off[j] + prefix;
        g_off[j]    = off;
        g_cursor[j] = off;
    }
    if (blk == 0 && tid == 0) g_off[N_NODES] = NCAND;
}

// ---------------------------------------------------------------------------
// Kernel 4: fill — one thread per ENTRY e writes all 3 records from one
// batch-row read. Order within a node is irrelevant (max over identical
// values is order-invariant -> deterministic output).
// ---------------------------------------------------------------------------
__global__ void fill_kernel(const int* __restrict__ batch) {
    int e = blockIdx.x * blockDim.x + threadIdx.x;
    if (e >= E_CNT) return;
    int b0 = batch[e * 3 + 0];
    int b1 = batch[e * 3 + 1];
    int b2 = batch[e * 3 + 2];
    int p0 = atomicAdd(&g_cursor[b0], 1);
    g_rec[p0] = make_int4(e,             b1, b2, 0);   // i=0: cols {1,2}
    int p1 = atomicAdd(&g_cursor[b1], 1);
    g_rec[p1] = make_int4(E_CNT + e,     b0, b2, 0);   // i=1: cols {0,2}
    int p2 = atomicAdd(&g_cursor[b2], 1);
    g_rec[p2] = make_int4(2 * E_CNT + e, b0, b1, 0);   // i=2: cols {0,1}
}

// ---------------------------------------------------------------------------
// Kernel 5: gather — ONE WARP PER NODE (8 nodes / 256-thread block).
// Lanes cover D in float4 chunks; the warp holds all 4 head accumulators in
// registers, loops over the node's candidates with a 1-deep record prefetch,
// then applies residual + leaky-relu and stores directly. No smem, no sync.
// ---------------------------------------------------------------------------
__global__ void __launch_bounds__(32 * NODES_PER_BLK) gather_kernel(
    const float* __restrict__ feats,   // [N, 128]
    const float* __restrict__ w,       // [3E, 4, 2]
    float*       __restrict__ out)     // [N, 4, 128]
{
    const int wid  = threadIdx.x >> 5;
    const int lane = threadIdx.x & 31;
    const int node = blockIdx.x * NODES_PER_BLK + wid;
    if (node >= N_NODES) return;
    const int d0 = lane << 2;

    const int start = g_off[node];
    const int end   = g_off[node + 1];

    const float NI = __int_as_float(0xff800000);
    float4 m0 = make_float4(NI, NI, NI, NI);
    float4 m1 = m0, m2 = m0, m3 = m0;

    int4 r = g_rec[start];                    // every node non-empty
    for (int k = start; k < end; k++) {
        const float4 wa = *(const float4*)(w + (long)r.x * 8);      // heads 0,1
        const float4 wb = *(const float4*)(w + (long)r.x * 8 + 4);  // heads 2,3
        const float4 f0 = *(const float4*)(feats + (long)r.y * D_CNT + d0);
        const float4 f1 = *(const float4*)(feats + (long)r.z * D_CNT + d0);

        if (k + 1 < end) r = g_rec[k + 1];    // prefetch next record

        m0.x = fmaxf(m0.x, fmaf(wa.x, f0.x, wa.y * f1.x));
        m0.y = fmaxf(m0.y, fmaf(wa.x, f0.y, wa.y * f1.y));
        m0.z = fmaxf(m0.z, fmaf(wa.x, f0.z, wa.y * f1.z));
        m0.w = fmaxf(m0.w, fmaf(wa.x, f0.w, wa.y * f1.w));

        m1.x = fmaxf(m1.x, fmaf(wa.z, f0.x, wa.w * f1.x));
        m1.y = fmaxf(m1.y, fmaf(wa.z, f0.y, wa.w * f1.y));
        m1.z = fmaxf(m1.z, fmaf(wa.z, f0.z, wa.w * f1.z));
        m1.w = fmaxf(m1.w, fmaf(wa.z, f0.w, wa.w * f1.w));

        m2.x = fmaxf(m2.x, fmaf(wb.x, f0.x, wb.y * f1.x));
        m2.y = fmaxf(m2.y, fmaf(wb.x, f0.y, wb.y * f1.y));
        m2.z = fmaxf(m2.z, fmaf(wb.x, f0.z, wb.y * f1.z));
        m2.w = fmaxf(m2.w, fmaf(wb.x, f0.w, wb.y * f1.w));

        m3.x = fmaxf(m3.x, fmaf(wb.z, f0.x, wb.w * f1.x));
        m3.y = fmaxf(m3.y, fmaf(wb.z, f0.y, wb.w * f1.y));
        m3.z = fmaxf(m3.z, fmaf(wb.z, f0.z, wb.w * f1.z));
        m3.w = fmaxf(m3.w, fmaf(wb.z, f0.w, wb.w * f1.w));
    }

    const float4 f = *(const float4*)(feats + (long)node * D_CNT + d0);
    float* ob = out + (long)node * (H_CNT * D_CNT) + d0;

    float4 v;
    v.x = m0.x + f.x; v.y = m0.y + f.y; v.z = m0.z + f.z; v.w = m0.w + f.w;
    v.x = (v.x >= 0.f) ? v.x : ALPHA * v.x;  v.y = (v.y >= 0.f) ? v.y : ALPHA * v.y;
    v.z = (v.z >= 0.f) ? v.z : ALPHA * v.z;  v.w = (v.w >= 0.f) ? v.w : ALPHA * v.w;
    *(float4*)(ob + 0 * D_CNT) = v;

    v.x = m1.x + f.x; v.y = m1.y + f.y; v.z = m1.z + f.z; v.w = m1.w + f.w;
    v.x = (v.x >= 0.f) ? v.x : ALPHA * v.x;  v.y = (v.y >= 0.f) ? v.y : ALPHA * v.y;
    v.z = (v.z >= 0.f) ? v.z : ALPHA * v.z;  v.w = (v.w >= 0.f) ? v.w : ALPHA * v.w;
    *(float4*)(ob + 1 * D_CNT) = v;

    v.x = m2.x + f.x; v.y = m2.y + f.y; v.z = m2.z + f.z; v.w = m2.w + f.w;
    v.x = (v.x >= 0.f) ? v.x : ALPHA * v.x;  v.y = (v.y >= 0.f) ? v.y : ALPHA * v.y;
    v.z = (v.z >= 0.f) ? v.z : ALPHA * v.z;  v.w = (v.w >= 0.f) ? v.w : ALPHA * v.w;
    *(float4*)(ob + 2 * D_CNT) = v;

    v.x = m3.x + f.x; v.y = m3.y + f.y; v.z = m3.z + f.z; v.w = m3.w + f.w;
    v.x = (v.x >= 0.f) ? v.x : ALPHA * v.x;  v.y = (v.y >= 0.f) ? v.y : ALPHA * v.y;
    v.z = (v.z >= 0.f) ? v.z : ALPHA * v.z;  v.w = (v.w >= 0.f) ? v.w : ALPHA * v.w;
    *(float4*)(ob + 3 * D_CNT) = v;
}

extern "C" void kernel_launch(void* const* d_in, const int* in_sizes, int n_in,
                              void* d_out, int out_size) {
    const int*   batch = (const int*)  d_in[0];   // [E, 3] int32
    const float* feats = (const float*)d_in[1];   // [N, 128] f32
    const float* w     = (const float*)d_in[2];   // [3E, 4, 2] f32
    float*       out   = (float*)d_out;           // [N, 512] f32

    hist_kernel <<<(E_CNT + 255) / 256, 256>>>(batch);
    scanA_kernel<<<NTILES, SCAN_B>>>();
    scanB_kernel<<<NTILES, SCAN_B>>>();
    fill_kernel <<<(E_CNT + 255) / 256, 256>>>(batch);
    gather_kernel<<<(N_NODES + NODES_PER_BLK - 1) / NODES_PER_BLK,
                    32 * NODES_PER_BLK>>>(feats, w, out);
}

// round 9
// speedup vs baseline: 2.6472x; 1.0793x over previous
#include <cuda_runtime.h>
#include <cstdint>

#define E_CNT   100000
#define N_NODES 50000
#define H_CNT   4
#define D_CNT   128
#define NCAND   (3 * E_CNT)          // 300000 candidate (entry, type) pairs
#define ALPHA   0.2f
#define SCAN_B  1024
#define NTILES  ((N_NODES + SCAN_B - 1) / SCAN_B)   // 49
#define NODES_PER_BLK 8              // warp-per-node gather

// ---------------------------------------------------------------------------
// Scratch (device globals; zero-initialized at module load. Every run leaves
// g_count back at zero — scanA consumes-and-clears it — so graph replays see
// identical state).
// ---------------------------------------------------------------------------
__device__ int  g_count [N_NODES];       // candidates per node (zeroed by scanA)
__device__ int  g_off   [N_NODES + 1];   // global start offsets
__device__ int  g_cursor[N_NODES];       // fill cursors
__device__ int  g_bsum  [NTILES];        // per-tile totals
__device__ int4 g_rec   [NCAND];         // {t, n0, n1, 0} grouped by node

// ---------------------------------------------------------------------------
// Kernel 1: histogram — one thread per ENTRY e; 3 counter bumps from one
// 12-byte batch-row read. Relies on g_count == 0 on entry.
// ---------------------------------------------------------------------------
__global__ void hist_kernel(const int* __restrict__ batch) {
    int e = blockIdx.x * blockDim.x + threadIdx.x;
    if (e >= E_CNT) return;
    int b0 = batch[e * 3 + 0];
    int b1 = batch[e * 3 + 1];
    int b2 = batch[e * 3 + 2];
    atomicAdd(&g_count[b0], 1);
    atomicAdd(&g_count[b1], 1);
    atomicAdd(&g_count[b2], 1);
}

// ---------------------------------------------------------------------------
// Kernel 2 (scanA): 49 blocks x 1024. Coalesced tile load of counts, zero
// the counts, block-local exclusive scan via warp shuffles.
// ---------------------------------------------------------------------------
__global__ void __launch_bounds__(SCAN_B) scanA_kernel() {
    __shared__ int ws[32];
    const int tid = threadIdx.x;
    const int j   = blockIdx.x * SCAN_B + tid;
    const int lane = tid & 31, wid = tid >> 5;

    int c = 0;
    if (j < N_NODES) { c = g_count[j]; g_count[j] = 0; }

    int v = c;
    #pragma unroll
    for (int o = 1; o < 32; o <<= 1) {
        int t = __shfl_up_sync(0xffffffffu, v, o);
        if (lane >= o) v += t;
    }
    if (lane == 31) ws[wid] = v;
    __syncthreads();
    if (wid == 0) {
        int s = ws[lane];
        #pragma unroll
        for (int o = 1; o < 32; o <<= 1) {
            int t = __shfl_up_sync(0xffffffffu, s, o);
            if (lane >= o) s += t;
        }
        ws[lane] = s;
    }
    __syncthreads();

    int excl = v - c + (wid ? ws[wid - 1] : 0);
    if (j < N_NODES) g_off[j] = excl;
    if (tid == SCAN_B - 1) g_bsum[blockIdx.x] = excl + c;
}

// ---------------------------------------------------------------------------
// Kernel 3 (scanB): add tile prefixes (<=48 values, one warp per block),
// materialize cursors and the end sentinel.
// ---------------------------------------------------------------------------
__global__ void __launch_bounds__(SCAN_B) scanB_kernel() {
    __shared__ int s_prefix;
    const int tid = threadIdx.x;
    const int blk = blockIdx.x;

    if (tid < 32) {
        int s = 0;
        if (tid      < blk) s += g_bsum[tid];
        if (tid + 32 < blk) s += g_bsum[tid + 32];
        #pragma unroll
        for (int o = 16; o > 0; o >>= 1)
            s += __shfl_down_sync(0xffffffffu, s, o);
        if (tid == 0) s_prefix = s;
    }
    __syncthreads();
    const int prefix = s_prefix;

    int j = blk * SCAN_B + tid;
    if (j < N_NODES) {
        int off = g_off[j] + prefix;
        g_off[j]    = off;
        g_cursor[j] = off;
    }
    if (blk == 0 && tid == 0) g_off[N_NODES] = NCAND;
}

// ---------------------------------------------------------------------------
// Kernel 4: fill — one thread per ENTRY e writes all 3 records from one
// batch-row read. Order within a node is irrelevant (max over identical
// values is order-invariant -> deterministic output). 128-thread blocks to
// spread warps over more SMs (latency-bound kernel).
// ---------------------------------------------------------------------------
__global__ void fill_kernel(const int* __restrict__ batch) {
    int e = blockIdx.x * blockDim.x + threadIdx.x;
    if (e >= E_CNT) return;
    int b0 = batch[e * 3 + 0];
    int b1 = batch[e * 3 + 1];
    int b2 = batch[e * 3 + 2];
    int p0 = atomicAdd(&g_cursor[b0], 1);
    g_rec[p0] = make_int4(e,             b1, b2, 0);   // i=0: cols {1,2}
    int p1 = atomicAdd(&g_cursor[b1], 1);
    g_rec[p1] = make_int4(E_CNT + e,     b0, b2, 0);   // i=1: cols {0,2}
    int p2 = atomicAdd(&g_cursor[b2], 1);
    g_rec[p2] = make_int4(2 * E_CNT + e, b0, b1, 0);   // i=2: cols {0,1}
}

// ---------------------------------------------------------------------------
// Candidate compute helper: all 4 heads, one float4 D-chunk.
// ---------------------------------------------------------------------------
__device__ __forceinline__ void cand_step(
    const float* __restrict__ feats, const float* __restrict__ w,
    const int4 r, const int d0,
    float4& m0, float4& m1, float4& m2, float4& m3)
{
    const float4 wa = *(const float4*)(w + (long)r.x * 8);      // heads 0,1
    const float4 wb = *(const float4*)(w + (long)r.x * 8 + 4);  // heads 2,3
    const float4 f0 = *(const float4*)(feats + (long)r.y * D_CNT + d0);
    const float4 f1 = *(const float4*)(feats + (long)r.z * D_CNT + d0);

    m0.x = fmaxf(m0.x, fmaf(wa.x, f0.x, wa.y * f1.x));
    m0.y = fmaxf(m0.y, fmaf(wa.x, f0.y, wa.y * f1.y));
    m0.z = fmaxf(m0.z, fmaf(wa.x, f0.z, wa.y * f1.z));
    m0.w = fmaxf(m0.w, fmaf(wa.x, f0.w, wa.y * f1.w));

    m1.x = fmaxf(m1.x, fmaf(wa.z, f0.x, wa.w * f1.x));
    m1.y = fmaxf(m1.y, fmaf(wa.z, f0.y, wa.w * f1.y));
    m1.z = fmaxf(m1.z, fmaf(wa.z, f0.z, wa.w * f1.z));
    m1.w = fmaxf(m1.w, fmaf(wa.z, f0.w, wa.w * f1.w));

    m2.x = fmaxf(m2.x, fmaf(wb.x, f0.x, wb.y * f1.x));
    m2.y = fmaxf(m2.y, fmaf(wb.x, f0.y, wb.y * f1.y));
    m2.z = fmaxf(m2.z, fmaf(wb.x, f0.z, wb.y * f1.z));
    m2.w = fmaxf(m2.w, fmaf(wb.x, f0.w, wb.y * f1.w));

    m3.x = fmaxf(m3.x, fmaf(wb.z, f0.x, wb.w * f1.x));
    m3.y = fmaxf(m3.y, fmaf(wb.z, f0.y, wb.w * f1.y));
    m3.z = fmaxf(m3.z, fmaf(wb.z, f0.z, wb.w * f1.z));
    m3.w = fmaxf(m3.w, fmaf(wb.z, f0.w, wb.w * f1.w));
}

// ---------------------------------------------------------------------------
// Kernel 5: gather — one warp per node, candidate loop unrolled x2 so each
// pair's records and then all 8 downstream loads issue together (MLP ~6),
// halving exposed L2 round-trips. Fused residual + leaky-relu epilogue.
// ---------------------------------------------------------------------------
__global__ void __launch_bounds__(32 * NODES_PER_BLK) gather_kernel(
    const float* __restrict__ feats,   // [N, 128]
    const float* __restrict__ w,       // [3E, 4, 2]
    float*       __restrict__ out)     // [N, 4, 128]
{
    const int wid  = threadIdx.x >> 5;
    const int lane = threadIdx.x & 31;
    const int node = blockIdx.x * NODES_PER_BLK + wid;   // grid exact: 6250*8
    const int d0 = lane << 2;

    const int start = g_off[node];
    const int end   = g_off[node + 1];

    const float NI = __int_as_float(0xff800000);
    float4 m0 = make_float4(NI, NI, NI, NI);
    float4 m1 = m0, m2 = m0, m3 = m0;

    int k = start;
    for (; k + 1 < end; k += 2) {
        const int4 ra = g_rec[k];
        const int4 rb = g_rec[k + 1];
        cand_step(feats, w, ra, d0, m0, m1, m2, m3);
        cand_step(feats, w, rb, d0, m0, m1, m2, m3);
    }
    if (k < end) {
        const int4 ra = g_rec[k];
        cand_step(feats, w, ra, d0, m0, m1, m2, m3);
    }

    const float4 f = *(const float4*)(feats + (long)node * D_CNT + d0);
    float* ob = out + (long)node * (H_CNT * D_CNT) + d0;

    float4 v;
    v.x = m0.x + f.x; v.y = m0.y + f.y; v.z = m0.z + f.z; v.w = m0.w + f.w;
    v.x = (v.x >= 0.f) ? v.x : ALPHA * v.x;  v.y = (v.y >= 0.f) ? v.y : ALPHA * v.y;
    v.z = (v.z >= 0.f) ? v.z : ALPHA * v.z;  v.w = (v.w >= 0.f) ? v.w : ALPHA * v.w;
    *(float4*)(ob + 0 * D_CNT) = v;

    v.x = m1.x + f.x; v.y = m1.y + f.y; v.z = m1.z + f.z; v.w = m1.w + f.w;
    v.x = (v.x >= 0.f) ? v.x : ALPHA * v.x;  v.y = (v.y >= 0.f) ? v.y : ALPHA * v.y;
    v.z = (v.z >= 0.f) ? v.z : ALPHA * v.z;  v.w = (v.w >= 0.f) ? v.w : ALPHA * v.w;
    *(float4*)(ob + 1 * D_CNT) = v;

    v.x = m2.x + f.x; v.y = m2.y + f.y; v.z = m2.z + f.z; v.w = m2.w + f.w;
    v.x = (v.x >= 0.f) ? v.x : ALPHA * v.x;  v.y = (v.y >= 0.f) ? v.y : ALPHA * v.y;
    v.z = (v.z >= 0.f) ? v.z : ALPHA * v.z;  v.w = (v.w >= 0.f) ? v.w : ALPHA * v.w;
    *(float4*)(ob + 2 * D_CNT) = v;

    v.x = m3.x + f.x; v.y = m3.y + f.y; v.z = m3.z + f.z; v.w = m3.w + f.w;
    v.x = (v.x >= 0.f) ? v.x : ALPHA * v.x;  v.y = (v.y >= 0.f) ? v.y : ALPHA * v.y;
    v.z = (v.z >= 0.f) ? v.z : ALPHA * v.z;  v.w = (v.w >= 0.f) ? v.w : ALPHA * v.w;
    *(float4*)(ob + 3 * D_CNT) = v;
}

extern "C" void kernel_launch(void* const* d_in, const int* in_sizes, int n_in,
                              void* d_out, int out_size) {
    const int*   batch = (const int*)  d_in[0];   // [E, 3] int32
    const float* feats = (const float*)d_in[1];   // [N, 128] f32
    const float* w     = (const float*)d_in[2];   // [3E, 4, 2] f32
    float*       out   = (float*)d_out;           // [N, 512] f32

    hist_kernel <<<(E_CNT + 255) / 256, 256>>>(batch);
    scanA_kernel<<<NTILES, SCAN_B>>>();
    scanB_kernel<<<NTILES, SCAN_B>>>();
    fill_kernel <<<(E_CNT + 127) / 128, 128>>>(batch);
    gather_kernel<<<N_NODES / NODES_PER_BLK, 32 * NODES_PER_BLK>>>(feats, w, out);
}